// round 13
// baseline (speedup 1.0000x reference)
#include <cuda_runtime.h>

// Micromagnetic LLG RK4 solver — Round 13: R12's tag-in-data neighbor sync
// + 4-LAYER STAGE-SPLIT mapping: 2x warps/SM at IDENTICAL instruction count.
// 128 CTAs x 1024 threads; CTA r owns global rows {2r, 2r+1}. Window rows
// 0..5 = global 2r-2 .. 2r+3. Layers ty = tid>>8:
//   odd stages (1,3; rows 1..4): layer ty computes window row 1+ty.
//   even stages (2,4; rows 2,3): owner layers ty<2 compute row 2+ty (their
//   owned global row 2r+ty), accumulate RK4, publish tagged m/u2.
//   halo polls: layer ty polls ONE cell (window row {0,1,4,5}).
// k1/k3 at own rows are computed by helper layers and passed bitwise through
// a small smem slot (KT) — arithmetic identical to R12 (rel_err 0.0).
// Sync = R12's tag-in-.w scheme: m double-buffered by tag parity, u2 single
// buffer (gated by interleaved m publishes), tag bases persist in g_base.

#define NXg 256
#define NYg 256
#define PLANE (NXg * NYg)
#define TSTEPS 256
#define NSIG 2
#define NSRC 3
#define NPROBE 5
#define RELAXN 100
#define NBLK 128
#define NT 1024
#define SROW 258
#define SMEM_BYTES (20 * SROW * 16)

__device__ float4 g_mbuf[2][PLANE];
__device__ float4 g_u2[PLANE];
__device__ unsigned g_base[NBLK * 8];   // [8r]=m count, [8r+1]=u2 count

__device__ __forceinline__ float4 ldcg4(const float4* p) {
    float4 v;
    asm volatile("ld.global.cg.v4.f32 {%0,%1,%2,%3}, [%4];"
                 : "=f"(v.x), "=f"(v.y), "=f"(v.z), "=f"(v.w)
                 : "l"(p) : "memory");
    return v;
}
__device__ __forceinline__ void stcg4(float4* p, float4 v) {
    asm volatile("st.global.cg.v4.f32 [%0], {%1,%2,%3,%4};"
                 :: "l"(p), "f"(v.x), "f"(v.y), "f"(v.z), "f"(v.w)
                 : "memory");
}

// Poll one tagged cell until it carries tag >= TAG (wraparound-safe).
#define POLL1(P, TAG, V)                                                       \
  { V = ldcg4(P);                                                              \
    while ((int)(__float_as_int(V.w) - (int)(TAG)) < 0) V = ldcg4(P); }

__device__ __forceinline__ float3 lap_torque(
    float ux, float uy, float uz,
    float sx, float sy, float sz,          // N+S+W+E sums
    float bx, float by, float bz_,         // bz_ already includes source
    float CEx, float CD, float alpha, float inv)
{
    float lx = sx - 4.0f * ux, ly = sy - 4.0f * uy, lz = sz - 4.0f * uz;
    float Bx = bx + CEx * lx;
    float By = by + CEx * ly;
    float Bz = bz_ + CEx * lz - CD * uz;
    float c1x = uy * Bz - uz * By;
    float c1y = uz * Bx - ux * Bz;
    float c1z = ux * By - uy * Bx;
    float c2x = uy * c1z - uz * c1y;
    float c2y = uz * c1x - ux * c1z;
    float c2z = ux * c1y - uy * c1x;
    const float CS = 1.0e-4f;
    float3 t;
    t.x = -inv * (c1x + alpha * c2x) + CS * (ux * uy);
    t.y = -inv * (c1y + alpha * c2y) + CS * (-(uz * uz + ux * ux));
    t.z = -inv * (c1z + alpha * c2z) + CS * (uy * uz);
    return t;
}

#define U(b, L) (smf4 + ((b) * 6 + (L)) * SROW)
#define KT(i)   (smf4 + (18 + (i)) * SROW)

// One full RK4 step. Entry: neighbors' m (tag ms) published; own m in mo.
#define STEPK()                                                                \
 { /* m poll + window fill */                                                  \
   { float4 v; POLL1(&g_mbuf[ms & 1u][pHP], ms, v);                            \
     U(0, HP)[c + 1] = v;                                                      \
     if (owner) U(0, RE)[c + 1] = make_float4(mox, moy, moz, 0.0f); }          \
   __syncthreads();                                                            \
   /* stage 1: all layers, window row RO */                                    \
   float mbx, mby, mbz;                                                        \
   { float4 cv = U(0, RO)[c + 1];                                              \
     mbx = cv.x; mby = cv.y; mbz = cv.z;                                       \
     float4 nN = U(0, RO - 1)[c + 1], nS = U(0, RO + 1)[c + 1];                \
     float4 nW = U(0, RO)[wOff], nE = U(0, RO)[eOff];                          \
     float3 k1 = lap_torque(mbx, mby, mbz,                                     \
         nN.x + nS.x + nW.x + nE.x, nN.y + nS.y + nW.y + nE.y,                 \
         nN.z + nS.z + nW.z + nE.z, bxo, byo, bzallO, CEx, CD, alpha, inv);    \
     U(1, RO)[c + 1] = make_float4(mbx + h2 * k1.x, mby + h2 * k1.y,           \
                                   mbz + h2 * k1.z, 0.0f);                     \
     if (ty == 1 || ty == 2)                                                   \
         KT(ty - 1)[c + 1] = make_float4(k1.x, k1.y, k1.z, 0.0f); }            \
   __syncthreads();                                                            \
   /* stage 2: owners (row RE) + tagged u2 publish; all layers poll u2 */      \
   float ax, ay, az;                                                           \
   us++;                                                                       \
   if (owner) {                                                                \
     float4 ct = U(1, RE)[c + 1];                                              \
     float4 nN = U(1, RE - 1)[c + 1], nS = U(1, RE + 1)[c + 1];                \
     float4 nW = U(1, RE)[wOff], nE = U(1, RE)[eOff];                          \
     float3 k2 = lap_torque(ct.x, ct.y, ct.z,                                  \
         nN.x + nS.x + nW.x + nE.x, nN.y + nS.y + nW.y + nE.y,                 \
         nN.z + nS.z + nW.z + nE.z, bxe, bye, bzallE, CEx, CD, alpha, inv);    \
     float4 u2v = make_float4(mox + h2 * k2.x, moy + h2 * k2.y,                \
                              moz + h2 * k2.z, __int_as_float((int)us));       \
     stcg4(&g_u2[gcown], u2v);                                                 \
     U(2, RE)[c + 1] = u2v;                                                    \
     float4 kt = KT(ty)[c + 1];                                                \
     ax = kt.x; ay = kt.y; az = kt.z;                                          \
     ax += 2.0f * k2.x; ay += 2.0f * k2.y; az += 2.0f * k2.z;                  \
   }                                                                           \
   { float4 w; POLL1(&g_u2[pHP], us, w); U(2, HP)[c + 1] = w; }                \
   __syncthreads();                                                            \
   /* stage 3: all layers, window row RO */                                    \
   { float4 ct = U(2, RO)[c + 1];                                              \
     float4 nN = U(2, RO - 1)[c + 1], nS = U(2, RO + 1)[c + 1];                \
     float4 nW = U(2, RO)[wOff], nE = U(2, RO)[eOff];                          \
     float3 k3 = lap_torque(ct.x, ct.y, ct.z,                                  \
         nN.x + nS.x + nW.x + nE.x, nN.y + nS.y + nW.y + nE.y,                 \
         nN.z + nS.z + nW.z + nE.z, bxo, byo, bzallO, CEx, CD, alpha, inv);    \
     U(1, RO)[c + 1] = make_float4(mbx + hh * k3.x, mby + hh * k3.y,           \
                                   mbz + hh * k3.z, 0.0f);                     \
     if (ty == 1 || ty == 2)                                                   \
         KT(ty - 1)[c + 1] = make_float4(k3.x, k3.y, k3.z, 0.0f); }            \
   __syncthreads();                                                            \
   /* stage 4: owners; final combine + tagged m publish */                     \
   ms++;                                                                       \
   if (owner) {                                                                \
     float4 ct = U(1, RE)[c + 1];                                              \
     float4 nN = U(1, RE - 1)[c + 1], nS = U(1, RE + 1)[c + 1];                \
     float4 nW = U(1, RE)[wOff], nE = U(1, RE)[eOff];                          \
     float3 k4 = lap_torque(ct.x, ct.y, ct.z,                                  \
         nN.x + nS.x + nW.x + nE.x, nN.y + nS.y + nW.y + nE.y,                 \
         nN.z + nS.z + nW.z + nE.z, bxe, bye, bzallE, CEx, CD, alpha, inv);    \
     float4 kt = KT(ty)[c + 1];                                                \
     ax += 2.0f * kt.x; ay += 2.0f * kt.y; az += 2.0f * kt.z;                  \
     ax += k4.x; ay += k4.y; az += k4.z;                                       \
     mox += h6 * ax; moy += h6 * ay; moz += h6 * az;                           \
     stcg4(&g_mbuf[ms & 1u][gcown],                                            \
           make_float4(mox, moy, moz, __int_as_float((int)ms)));               \
   } }

__global__ void __launch_bounds__(NT, 1)
mm_kernel(const float* __restrict__ sig, const float* __restrict__ Bext,
          const float* __restrict__ MsatP, const int* __restrict__ srcP,
          const int* __restrict__ probeP, const int* __restrict__ finalP,
          float* __restrict__ out)
{
    extern __shared__ float4 smf4[];

    const int tid  = threadIdx.x;
    const int c    = tid & 255;
    const int ty   = tid >> 8;              // 0..3, warp-uniform
    const bool owner = (ty < 2);
    const int r    = blockIdx.x;

    // Clamped in-row W/E smem indices (center at c+1).
    const int wOff = (c == 0) ? 1 : c;
    const int eOff = (c == 255) ? 256 : c + 2;

    // Window rows: odd-stage row RO = 1+ty; owner row RE = 2+ty; poll row HP.
    const int RO = 1 + ty;
    const int RE = 2 + ty;                  // meaningful for owners
    const int HP = owner ? ty : ty + 2;     // {0,1,4,5}

    int g;
    g = 2 * r - 1 + ty;                     // global for RO
    const int gRO = g < 0 ? 0 : (g > NXg - 1 ? NXg - 1 : g);
    g = 2 * r - 2 + HP;                     // global for HP
    const int gHP = g < 0 ? 0 : (g > NXg - 1 ? NXg - 1 : g);
    const int gRE  = 2 * r + ty;            // owners: always in range
    const int gREc = owner ? gRE : 0;       // safe index for loads
    const int pHP  = gHP * NYg + c;         // polled cell
    const int gcown = gREc * NYg + c;       // publish cell (owners)

    // Tag bases (own sector; persisted at run end; uniform across CTAs).
    unsigned ms = g_base[8 * r];
    unsigned us = g_base[8 * r + 1];

    const float Msat = *MsatP;
    const float CEx = (float)(2.0 * 3.5e-12 / ((double)Msat * (5e-8 * 5e-8)));
    const float CD  = (float)(4e-7 * 3.14159265358979323846 * (double)Msat);
    const float hh  = (float)(175950000000.0 * 5e-12);   // GAMMA_LL * DT
    const float h2  = 0.5f * hh;
    const float h6  = hh * (1.0f / 6.0f);
    const int final_board = *finalP;

    // B_ext at RO (all) and RE (owners).
    const int oRO = gRO * NYg + c;
    const float bxo = __ldg(Bext + 0 * PLANE + oRO);
    const float byo = __ldg(Bext + 1 * PLANE + oRO);
    const float bzo = __ldg(Bext + 2 * PLANE + oRO);
    const float bxe = __ldg(Bext + 0 * PLANE + gcown);
    const float bye = __ldg(Bext + 1 * PLANE + gcown);
    const float bze = __ldg(Bext + 2 * PLANE + gcown);

    // Source ids at RO / RE cells.
    int sidO = -1, sidE = -1;
    {
        int s0r = srcP[0], s0c = srcP[1];
        int s1r = srcP[2], s1c = srcP[3];
        int s2r = srcP[4], s2c = srcP[5];
        sidO = (gRO == s0r && c == s0c) ? 0 :
               (gRO == s1r && c == s1c) ? 1 :
               (gRO == s2r && c == s2c) ? 2 : -1;
        sidE = (gRE == s0r && c == s0c) ? 0 :
               (gRE == s1r && c == s1c) ? 1 :
               (gRE == s2r && c == s2c) ? 2 : -1;
    }
    // Probe id at owned cell.
    int pid = -1;
    if (owner) {
        #pragma unroll
        for (int k = 0; k < NPROBE; k++)
            if (probeP[2 * k] == gRE && probeP[2 * k + 1] == c) pid = k;
    }

    float mox = 0.0f, moy = 1.0f, moz = 0.0f;   // owners' m
    float bzallO = bzo, bzallE = bze;           // bz + source, per step

    // ---- init: m0 = (0,1,0); tagged publish ----
    ms++;
    if (owner)
        stcg4(&g_mbuf[ms & 1u][gcown],
              make_float4(mox, moy, moz, __int_as_float((int)ms)));

    // ---- relax phase: alpha = 0.5, no source ----
    {
        const float alpha = 0.5f;
        const float inv = 1.0f / (1.0f + alpha * alpha);
        for (int s = 0; s < RELAXN; s++) {
            STEPK();
        }
    }
    const float mrx = mox, mry = moy, mrz = moz;   // m_relaxed (owners)

    // ---- driven phase: alpha = 0.01 ----
    {
        const float alpha = 0.01f;
        const float inv = 1.0f / (1.0f + alpha * alpha);
        for (int sgn = 0; sgn < NSIG; sgn++) {
            if (sgn > 0) {   // reset to m_relaxed (tagged publish event)
                ms++;
                if (owner) {
                    mox = mrx; moy = mry; moz = mrz;
                    stcg4(&g_mbuf[ms & 1u][gcown],
                          make_float4(mox, moy, moz,
                                      __int_as_float((int)ms)));
                }
            }
            for (int t = 0; t < TSTEPS; t++) {
                const float* sp = sig + (sgn * TSTEPS + t) * NSRC;
                float sv0 = __ldg(sp + 0), sv1 = __ldg(sp + 1),
                      sv2 = __ldg(sp + 2);
                bzallO = bzo + ((sidO == 0) ? sv0 :
                                (sidO == 1) ? sv1 :
                                (sidO == 2) ? sv2 : 0.0f);
                bzallE = bze + ((sidE == 0) ? sv0 :
                                (sidE == 1) ? sv1 :
                                (sidE == 2) ? sv2 : 0.0f);
                STEPK();
                if (pid >= 0) {
                    float val = final_board ? (moz - mrz) * Msat : moz;
                    out[(sgn * TSTEPS + t) * NPROBE + pid] = val;
                }
            }
        }
    }

    // Persist tag bases for the next graph replay (own slot only).
    if (tid == 0) {
        g_base[8 * r]     = ms;
        g_base[8 * r + 1] = us;
    }
}

extern "C" void kernel_launch(void* const* d_in, const int* in_sizes, int n_in,
                              void* d_out, int out_size) {
    const float* sig    = (const float*)d_in[0];  // (2, 256, 3)
    const float* Bext   = (const float*)d_in[1];  // (1, 3, 256, 256)
    const float* MsatP  = (const float*)d_in[2];  // scalar
    const int*   srcP   = (const int*)d_in[3];    // (3, 2)
    const int*   probeP = (const int*)d_in[4];    // (5, 2)
    const int*   finalP = (const int*)d_in[5];    // scalar
    float* out = (float*)d_out;                   // (2, 256, 5)
    (void)in_sizes; (void)n_in; (void)out_size;

    cudaFuncSetAttribute(mm_kernel,
                         cudaFuncAttributeMaxDynamicSharedMemorySize,
                         SMEM_BYTES);
    mm_kernel<<<NBLK, NT, SMEM_BYTES>>>(sig, Bext, MsatP, srcP, probeP,
                                        finalP, out);
}

// round 14
// speedup vs baseline: 1.0567x; 1.0567x over previous
#include <cuda_runtime.h>
#include <cstdint>

// Micromagnetic LLG RK4 solver — Round 14: R12's two-phase halo-2 stepping
// and tag-in-data neighbor sync, with an INSTRUCTION DIET on the compute:
// precomputed u32 smem addresses (buffer/N/S offsets fold into LDS [R+imm]
// immediates), scalar registers instead of float4 structs, flattened
// two-rows-per-thread stages. Values and operation order are bit-identical
// to R12 (rel_err 0.0).
// 128 CTAs x 512 threads; CTA r owns global rows {2r, 2r+1}; thread
// (ty = tid>>8, c = tid&255) owns cell (2r+ty, c). Window rows 0..5 =
// global 2r-2..2r+3. Odd stages: thread computes rows RA=2-ty, RB=4-ty;
// even stages: own row RE=2+ty. Polls: window rows ty and 4+ty.

#define NXg 256
#define NYg 256
#define PLANE (NXg * NYg)
#define TSTEPS 256
#define NSIG 2
#define NSRC 3
#define NPROBE 5
#define RELAXN 100
#define NBLK 128
#define NT 512
#define SROW 258
#define RBY 4128                 // row bytes = SROW * 16
#define BUFB (6 * RBY)           // per-buffer bytes (6 rows)
#define SMEM_BYTES (3 * BUFB)

__device__ float4 g_mbuf[2][PLANE];
__device__ float4 g_u2[PLANE];
__device__ unsigned g_base[NBLK * 8];   // [8r]=m count, [8r+1]=u2 count

__device__ __forceinline__ float4 ldcg4(const float4* p) {
    float4 v;
    asm volatile("ld.global.cg.v4.f32 {%0,%1,%2,%3}, [%4];"
                 : "=f"(v.x), "=f"(v.y), "=f"(v.z), "=f"(v.w)
                 : "l"(p) : "memory");
    return v;
}
__device__ __forceinline__ void stcg4(float4* p, float4 v) {
    asm volatile("st.global.cg.v4.f32 [%0], {%1,%2,%3,%4};"
                 :: "l"(p), "f"(v.x), "f"(v.y), "f"(v.z), "f"(v.w)
                 : "memory");
}
__device__ __forceinline__ void lds3(float& x, float& y, float& z,
                                     uint32_t a) {
    float w_;
    asm volatile("ld.shared.v4.f32 {%0,%1,%2,%3}, [%4];"
                 : "=f"(x), "=f"(y), "=f"(z), "=f"(w_) : "r"(a));
}
__device__ __forceinline__ void sts3(uint32_t a, float x, float y, float z) {
    asm volatile("st.shared.v4.f32 [%0], {%1,%2,%3,%4};"
                 :: "r"(a), "f"(x), "f"(y), "f"(z), "f"(0.0f));
}

// Poll two tagged cells until both carry tag >= TAG (wraparound-safe).
#define POLL2(P0, P2, TAG, V0, V2)                                             \
  { V0 = ldcg4(P0); V2 = ldcg4(P2);                                            \
    while (((int)(__float_as_int(V0.w) - (int)(TAG)) |                         \
            (int)(__float_as_int(V2.w) - (int)(TAG))) < 0) {                   \
        V0 = ldcg4(P0); V2 = ldcg4(P2);                                        \
    } }

__device__ __forceinline__ float3 lap_torque(
    float ux, float uy, float uz,
    float sx, float sy, float sz,          // N+S+W+E sums
    float bx, float by, float bz_,         // bz_ already includes source
    float CEx, float CD, float alpha, float inv)
{
    float lx = sx - 4.0f * ux, ly = sy - 4.0f * uy, lz = sz - 4.0f * uz;
    float Bx = bx + CEx * lx;
    float By = by + CEx * ly;
    float Bz = bz_ + CEx * lz - CD * uz;
    float c1x = uy * Bz - uz * By;
    float c1y = uz * Bx - ux * Bz;
    float c1z = ux * By - uy * Bx;
    float c2x = uy * c1z - uz * c1y;
    float c2y = uz * c1x - ux * c1z;
    float c2z = ux * c1y - uy * c1x;
    const float CS = 1.0e-4f;
    float3 t;
    t.x = -inv * (c1x + alpha * c2x) + CS * (ux * uy);
    t.y = -inv * (c1y + alpha * c2y) + CS * (-(uz * uz + ux * ux));
    t.z = -inv * (c1z + alpha * c2z) + CS * (uy * uz);
    return t;
}

// Torque at row with center base AC (buf offset BO compile-time), W/E bases.
#define TORQ(AC, AW, AE, BO, cx, cy, cz, bx_, by_, bz_, KV)                    \
  { float n1x, n1y, n1z, n2x, n2y, n2z, wx_, wy_, wz_, ex_, ey_, ez_;          \
    lds3(n1x, n1y, n1z, (AC) + (BO) - RBY);                                    \
    lds3(n2x, n2y, n2z, (AC) + (BO) + RBY);                                    \
    lds3(wx_, wy_, wz_, (AW) + (BO));                                          \
    lds3(ex_, ey_, ez_, (AE) + (BO));                                          \
    KV = lap_torque(cx, cy, cz,                                                \
        n1x + n2x + wx_ + ex_, n1y + n2y + wy_ + ey_, n1z + n2z + wz_ + ez_,   \
        bx_, by_, bz_, CEx, CD, alpha, inv); }

// One full RK4 step. Entry: own m in mo*; neighbors publishing tag ms.
#define STEPK()                                                                \
 { const float4* p0 = (ms & 1u) ? pm1H0 : pm0H0;                               \
   const float4* p4 = (ms & 1u) ? pm1H4 : pm0H4;                               \
   float4 v0, v2;                                                              \
   POLL2(p0, p4, ms, v0, v2);                                                  \
   sts3(aH0, v0.x, v0.y, v0.z);                                                \
   sts3(aH4, v2.x, v2.y, v2.z);                                                \
   sts3(aRE, mox, moy, moz);                                                   \
   __syncthreads();                                                            \
   /* stage 1: rows RA, RB from buf0 (centers in regs) */                      \
   const float cAx = ty ? v0.x : mox, cAy = ty ? v0.y : moy,                   \
               cAz = ty ? v0.z : moz;                                          \
   const float cBx = ty ? mox : v2.x, cBy = ty ? moy : v2.y,                   \
               cBz = ty ? moz : v2.z;                                          \
   float3 kA, kB;                                                              \
   TORQ(aRA, aRAw, aRAe, 0, cAx, cAy, cAz, bxA, byA, bzallA, kA);              \
   float u1Ax = cAx + h2 * kA.x, u1Ay = cAy + h2 * kA.y,                       \
         u1Az = cAz + h2 * kA.z;                                               \
   sts3(aRA + BUFB, u1Ax, u1Ay, u1Az);                                         \
   TORQ(aRB_, aRBw, aRBe, 0, cBx, cBy, cBz, bxB, byB, bzallB, kB);             \
   float u1Bx = cBx + h2 * kB.x, u1By = cBy + h2 * kB.y,                       \
         u1Bz = cBz + h2 * kB.z;                                               \
   sts3(aRB_ + BUFB, u1Bx, u1By, u1Bz);                                        \
   float ax = ty ? kB.x : kA.x, ay = ty ? kB.y : kA.y,                         \
         az = ty ? kB.z : kA.z;                                                \
   __syncthreads();                                                            \
   /* stage 2: own row RE from buf1; tagged u2 publish + poll */               \
   {  float cx2 = ty ? u1Bx : u1Ax, cy2 = ty ? u1By : u1Ay,                    \
            cz2 = ty ? u1Bz : u1Az;                                            \
      float3 k2;                                                               \
      TORQ(aRE, aREw, aREe, BUFB, cx2, cy2, cz2, bxE, byE, bzallE, k2);        \
      ax += 2.0f * k2.x; ay += 2.0f * k2.y; az += 2.0f * k2.z;                 \
      u2x = mox + h2 * k2.x; u2y = moy + h2 * k2.y; u2z = moz + h2 * k2.z; }   \
   us++;                                                                       \
   stcg4(&g_u2[gcown],                                                         \
         make_float4(u2x, u2y, u2z, __int_as_float((int)us)));                 \
   sts3(aRE + 2 * BUFB, u2x, u2y, u2z);                                        \
   float4 w0, w2;                                                              \
   POLL2(pu2H0, pu2H4, us, w0, w2);                                            \
   sts3(aH0 + 2 * BUFB, w0.x, w0.y, w0.z);                                     \
   sts3(aH4 + 2 * BUFB, w2.x, w2.y, w2.z);                                     \
   __syncthreads();                                                            \
   /* stage 3: rows RA, RB from buf2 (centers in regs) */                      \
   { const float dAx = ty ? w0.x : u2x, dAy = ty ? w0.y : u2y,                 \
                 dAz = ty ? w0.z : u2z;                                        \
     const float dBx = ty ? u2x : w2.x, dBy = ty ? u2y : w2.y,                 \
                 dBz = ty ? u2z : w2.z;                                        \
     TORQ(aRA, aRAw, aRAe, 2 * BUFB, dAx, dAy, dAz, bxA, byA, bzallA, kA);     \
     TORQ(aRB_, aRBw, aRBe, 2 * BUFB, dBx, dBy, dBz, bxB, byB, bzallB, kB); }  \
   float u3Ax = cAx + hh * kA.x, u3Ay = cAy + hh * kA.y,                       \
         u3Az = cAz + hh * kA.z;                                               \
   sts3(aRA + BUFB, u3Ax, u3Ay, u3Az);                                         \
   float u3Bx = cBx + hh * kB.x, u3By = cBy + hh * kB.y,                       \
         u3Bz = cBz + hh * kB.z;                                               \
   sts3(aRB_ + BUFB, u3Bx, u3By, u3Bz);                                        \
   ax += 2.0f * (ty ? kB.x : kA.x); ay += 2.0f * (ty ? kB.y : kA.y);           \
   az += 2.0f * (ty ? kB.z : kA.z);                                            \
   __syncthreads();                                                            \
   /* stage 4: own row RE from buf1; final combine + tagged m publish */       \
   { float cx4 = ty ? u3Bx : u3Ax, cy4 = ty ? u3By : u3Ay,                     \
           cz4 = ty ? u3Bz : u3Az;                                             \
     float3 k4;                                                                \
     TORQ(aRE, aREw, aREe, BUFB, cx4, cy4, cz4, bxE, byE, bzallE, k4);         \
     ax += k4.x; ay += k4.y; az += k4.z; }                                     \
   mox += h6 * ax; moy += h6 * ay; moz += h6 * az;                             \
   ms++;                                                                       \
   stcg4(&((ms & 1u) ? gm1 : gm0)[gcown],                                      \
         make_float4(mox, moy, moz, __int_as_float((int)ms))); }

__global__ void __launch_bounds__(NT, 1)
mm_kernel(const float* __restrict__ sig, const float* __restrict__ Bext,
          const float* __restrict__ MsatP, const int* __restrict__ srcP,
          const int* __restrict__ probeP, const int* __restrict__ finalP,
          float* __restrict__ out)
{
    extern __shared__ float4 smf4[];
    uint32_t S;
    asm("{ .reg .u64 t; cvta.to.shared.u64 t, %1; cvt.u32.u64 %0, t; }"
        : "=r"(S) : "l"(smf4));

    const int tid = threadIdx.x;
    const int c   = tid & 255;
    const int ty  = tid >> 8;               // 0/1, warp-uniform
    const int r   = blockIdx.x;

    // Smem addresses: center col at (c+1)*16; W/E deltas clamp at edges.
    const uint32_t cB = (uint32_t)(c + 1) * 16u;
    const int wD = (c == 0) ? 0 : -16;
    const int eD = (c == 255) ? 0 : 16;
    const uint32_t aRA  = S + (uint32_t)(2 - ty) * RBY + cB;
    const uint32_t aRB_ = S + (uint32_t)(4 - ty) * RBY + cB;
    const uint32_t aRE  = S + (uint32_t)(2 + ty) * RBY + cB;
    const uint32_t aRAw = aRA + wD,  aRAe = aRA + eD;
    const uint32_t aRBw = aRB_ + wD, aRBe = aRB_ + eD;
    const uint32_t aREw = aRE + wD,  aREe = aRE + eD;
    const uint32_t aH0  = S + (uint32_t)ty * RBY + cB;
    const uint32_t aH4  = S + (uint32_t)(4 + ty) * RBY + cB;

    // Global rows (clamped) and poll/publish cells.
    int g;
    g = 2 * r - 2 + ty;                 // window row ty (low poll)
    const int gH0 = g < 0 ? 0 : g;
    g = 2 * r + 2 + ty;                 // window row 4+ty (high poll)
    const int gH4 = g > NXg - 1 ? NXg - 1 : g;
    g = 2 * r - ty;                     // row RA = 2-ty -> global 2r-ty
    const int gRA = g < 0 ? 0 : (g > NXg - 1 ? NXg - 1 : g);
    g = 2 * r + 2 - ty;                 // row RB = 4-ty -> global 2r+2-ty
    const int gRB = g < 0 ? 0 : (g > NXg - 1 ? NXg - 1 : g);
    const int gRE = 2 * r + ty;         // own row (always in range)
    const int cH0 = gH0 * NYg + c;
    const int cH4 = gH4 * NYg + c;
    const int gcown = gRE * NYg + c;

    const float4* pm0H0 = &g_mbuf[0][cH0];
    const float4* pm1H0 = &g_mbuf[1][cH0];
    const float4* pm0H4 = &g_mbuf[0][cH4];
    const float4* pm1H4 = &g_mbuf[1][cH4];
    const float4* pu2H0 = &g_u2[cH0];
    const float4* pu2H4 = &g_u2[cH4];
    float4* gm0 = g_mbuf[0];
    float4* gm1 = g_mbuf[1];

    // Tag bases (own sector; persisted at run end; uniform across CTAs).
    unsigned ms = g_base[8 * r];
    unsigned us = g_base[8 * r + 1];

    const float Msat = *MsatP;
    const float CEx = (float)(2.0 * 3.5e-12 / ((double)Msat * (5e-8 * 5e-8)));
    const float CD  = (float)(4e-7 * 3.14159265358979323846 * (double)Msat);
    const float hh  = (float)(175950000000.0 * 5e-12);   // GAMMA_LL * DT
    const float h2  = 0.5f * hh;
    const float h6  = hh * (1.0f / 6.0f);
    const int final_board = *finalP;

    // B_ext at rows RA, RB, RE.
    const int oRA = gRA * NYg + c, oRB = gRB * NYg + c;
    const float bxA = __ldg(Bext + 0 * PLANE + oRA);
    const float byA = __ldg(Bext + 1 * PLANE + oRA);
    const float bzA = __ldg(Bext + 2 * PLANE + oRA);
    const float bxB = __ldg(Bext + 0 * PLANE + oRB);
    const float byB = __ldg(Bext + 1 * PLANE + oRB);
    const float bzB = __ldg(Bext + 2 * PLANE + oRB);
    const float bxE = __ldg(Bext + 0 * PLANE + gcown);
    const float byE = __ldg(Bext + 1 * PLANE + gcown);
    const float bzE = __ldg(Bext + 2 * PLANE + gcown);

    // Source ids at rows RA, RB, RE.
    int sidA, sidB, sidE;
    {
        int s0r = srcP[0], s0c = srcP[1];
        int s1r = srcP[2], s1c = srcP[3];
        int s2r = srcP[4], s2c = srcP[5];
        sidA = (gRA == s0r && c == s0c) ? 0 : (gRA == s1r && c == s1c) ? 1 :
               (gRA == s2r && c == s2c) ? 2 : -1;
        sidB = (gRB == s0r && c == s0c) ? 0 : (gRB == s1r && c == s1c) ? 1 :
               (gRB == s2r && c == s2c) ? 2 : -1;
        sidE = (gRE == s0r && c == s0c) ? 0 : (gRE == s1r && c == s1c) ? 1 :
               (gRE == s2r && c == s2c) ? 2 : -1;
    }
    // Probe id at owned cell.
    int pid = -1;
    #pragma unroll
    for (int k = 0; k < NPROBE; k++)
        if (probeP[2 * k] == gRE && probeP[2 * k + 1] == c) pid = k;

    float mox = 0.0f, moy = 1.0f, moz = 0.0f;    // own m
    float u2x, u2y, u2z;
    float bzallA = bzA, bzallB = bzB, bzallE = bzE;

    // ---- init: m0 = (0,1,0); tagged publish ----
    ms++;
    stcg4(&((ms & 1u) ? gm1 : gm0)[gcown],
          make_float4(mox, moy, moz, __int_as_float((int)ms)));

    // ---- relax phase: alpha = 0.5, no source ----
    {
        const float alpha = 0.5f;
        const float inv = 1.0f / (1.0f + alpha * alpha);
        for (int s = 0; s < RELAXN; s++) {
            STEPK();
        }
    }
    const float mrx = mox, mry = moy, mrz = moz;   // m_relaxed (own)

    // ---- driven phase: alpha = 0.01 ----
    {
        const float alpha = 0.01f;
        const float inv = 1.0f / (1.0f + alpha * alpha);
        for (int sgn = 0; sgn < NSIG; sgn++) {
            if (sgn > 0) {   // reset to m_relaxed (tagged publish event)
                mox = mrx; moy = mry; moz = mrz;
                ms++;
                stcg4(&((ms & 1u) ? gm1 : gm0)[gcown],
                      make_float4(mox, moy, moz, __int_as_float((int)ms)));
            }
            for (int t = 0; t < TSTEPS; t++) {
                const float* sp = sig + (sgn * TSTEPS + t) * NSRC;
                float sv0 = __ldg(sp + 0), sv1 = __ldg(sp + 1),
                      sv2 = __ldg(sp + 2);
                bzallA = bzA + ((sidA == 0) ? sv0 : (sidA == 1) ? sv1 :
                                (sidA == 2) ? sv2 : 0.0f);
                bzallB = bzB + ((sidB == 0) ? sv0 : (sidB == 1) ? sv1 :
                                (sidB == 2) ? sv2 : 0.0f);
                bzallE = bzE + ((sidE == 0) ? sv0 : (sidE == 1) ? sv1 :
                                (sidE == 2) ? sv2 : 0.0f);
                STEPK();
                if (pid >= 0) {
                    float val = final_board ? (moz - mrz) * Msat : moz;
                    out[(sgn * TSTEPS + t) * NPROBE + pid] = val;
                }
            }
        }
    }

    // Persist tag bases for the next graph replay (own slot only).
    if (tid == 0) {
        g_base[8 * r]     = ms;
        g_base[8 * r + 1] = us;
    }
}

extern "C" void kernel_launch(void* const* d_in, const int* in_sizes, int n_in,
                              void* d_out, int out_size) {
    const float* sig    = (const float*)d_in[0];  // (2, 256, 3)
    const float* Bext   = (const float*)d_in[1];  // (1, 3, 256, 256)
    const float* MsatP  = (const float*)d_in[2];  // scalar
    const int*   srcP   = (const int*)d_in[3];    // (3, 2)
    const int*   probeP = (const int*)d_in[4];    // (5, 2)
    const int*   finalP = (const int*)d_in[5];    // scalar
    float* out = (float*)d_out;                   // (2, 256, 5)
    (void)in_sizes; (void)n_in; (void)out_size;

    cudaFuncSetAttribute(mm_kernel,
                         cudaFuncAttributeMaxDynamicSharedMemorySize,
                         SMEM_BYTES);
    mm_kernel<<<NBLK, NT, SMEM_BYTES>>>(sig, Bext, MsatP, srcP, probeP,
                                        finalP, out);
}

// round 15
// speedup vs baseline: 1.0584x; 1.0016x over previous
#include <cuda_runtime.h>
#include <cstdint>

// Micromagnetic LLG RK4 solver — Round 15: FUSED-SIGNAL lockstep stepping.
// The two driven signals are independent sims from the same m_relaxed, so
// each thread carries BOTH sims' state and each step advances both: the
// serial latency chain (polls, bars, L2 rounds) is paid once for two sims,
// and the doubled independent FP/LDS work fills the issue stalls.
// 613 sync rounds -> 357 (1 init + 100 relax + 256 driven; per-signal
// resets vanish because both slots end relax exactly at m_relaxed).
// Everything else is the proven R12/R14 machinery: two-phase halo-2
// stepping, tag-in-.w neighbor sync (m parity-buffered, u2 single-buffered,
// monotonic tags persisted in g_base), precomputed smem addresses.
// 128 CTAs x 512 threads; CTA r owns global rows {2r,2r+1}; thread
// (ty = tid>>8, c = tid&255) owns cell (2r+ty, c) in both sims.

#define NXg 256
#define NYg 256
#define PLANE (NXg * NYg)
#define TSTEPS 256
#define NSRC 3
#define NPROBE 5
#define RELAXN 100
#define NBLK 128
#define NT 512
#define SROW 258
#define RBY 4128                  // row bytes = SROW * 16
#define BUFB (6 * RBY)            // per-buffer bytes (6 rows)
#define SIGB (3 * BUFB)           // per-sig smem block (3 buffers)
#define SMEM_BYTES (2 * SIGB)     // 148,608 B

__device__ float4 g_mbuf[2][2][PLANE];   // [parity][sig]
__device__ float4 g_u2[2][PLANE];        // [sig]
__device__ unsigned g_base[NBLK * 8];    // [8r]=m count, [8r+1]=u2 count

__device__ __forceinline__ float4 ldcg4(const float4* p) {
    float4 v;
    asm volatile("ld.global.cg.v4.f32 {%0,%1,%2,%3}, [%4];"
                 : "=f"(v.x), "=f"(v.y), "=f"(v.z), "=f"(v.w)
                 : "l"(p) : "memory");
    return v;
}
__device__ __forceinline__ void stcg4(float4* p, float4 v) {
    asm volatile("st.global.cg.v4.f32 [%0], {%1,%2,%3,%4};"
                 :: "l"(p), "f"(v.x), "f"(v.y), "f"(v.z), "f"(v.w)
                 : "memory");
}
__device__ __forceinline__ void lds3(float& x, float& y, float& z,
                                     uint32_t a) {
    float w_;
    asm volatile("ld.shared.v4.f32 {%0,%1,%2,%3}, [%4];"
                 : "=f"(x), "=f"(y), "=f"(z), "=f"(w_) : "r"(a));
}
__device__ __forceinline__ void sts3(uint32_t a, float x, float y, float z) {
    asm volatile("st.shared.v4.f32 [%0], {%1,%2,%3,%4};"
                 :: "r"(a), "f"(x), "f"(y), "f"(z), "f"(0.0f));
}

// Poll four tagged cells until all carry tag >= TAG (wraparound-safe).
#define POLL4(PA, PB, PC, PD, TAG, VA, VB, VC, VD)                             \
  { VA = ldcg4(PA); VB = ldcg4(PB); VC = ldcg4(PC); VD = ldcg4(PD);            \
    while (((int)(__float_as_int(VA.w) - (int)(TAG)) |                         \
            (int)(__float_as_int(VB.w) - (int)(TAG)) |                         \
            (int)(__float_as_int(VC.w) - (int)(TAG)) |                         \
            (int)(__float_as_int(VD.w) - (int)(TAG))) < 0) {                   \
        VA = ldcg4(PA); VB = ldcg4(PB); VC = ldcg4(PC); VD = ldcg4(PD);        \
    } }

__device__ __forceinline__ float3 lap_torque(
    float ux, float uy, float uz,
    float sx, float sy, float sz,          // N+S+W+E sums
    float bx, float by, float bz_,         // bz_ already includes source
    float CEx, float CD, float alpha, float inv)
{
    float lx = sx - 4.0f * ux, ly = sy - 4.0f * uy, lz = sz - 4.0f * uz;
    float Bx = bx + CEx * lx;
    float By = by + CEx * ly;
    float Bz = bz_ + CEx * lz - CD * uz;
    float c1x = uy * Bz - uz * By;
    float c1y = uz * Bx - ux * Bz;
    float c1z = ux * By - uy * Bx;
    float c2x = uy * c1z - uz * c1y;
    float c2y = uz * c1x - ux * c1z;
    float c2z = ux * c1y - uy * c1x;
    const float CS = 1.0e-4f;
    float3 t;
    t.x = -inv * (c1x + alpha * c2x) + CS * (ux * uy);
    t.y = -inv * (c1y + alpha * c2y) + CS * (-(uz * uz + ux * ux));
    t.z = -inv * (c1z + alpha * c2z) + CS * (uy * uz);
    return t;
}

// Torque at row with center base AC (+compile-time buffer offset BO).
#define TORQ(AC, AW, AE, BO, cx, cy, cz, bx_, by_, bz_, KV)                    \
  { float n1x, n1y, n1z, n2x, n2y, n2z, wx_, wy_, wz_, ex_, ey_, ez_;          \
    lds3(n1x, n1y, n1z, (AC) + (BO) - RBY);                                    \
    lds3(n2x, n2y, n2z, (AC) + (BO) + RBY);                                    \
    lds3(wx_, wy_, wz_, (AW) + (BO));                                          \
    lds3(ex_, ey_, ez_, (AE) + (BO));                                          \
    KV = lap_torque(cx, cy, cz,                                                \
        n1x + n2x + wx_ + ex_, n1y + n2y + wy_ + ey_, n1z + n2z + wz_ + ez_,   \
        bx_, by_, bz_, CEx, CD, alpha, inv); }

// One RK4 step advancing BOTH sims. Entry: own m in mo*[2]; tag ms current.
#define STEPK()                                                                \
 { float4 v0[2], v2[2];                                                        \
   { const float4* mb = g_mbuf[ms & 1u][0];                                    \
     POLL4(mb + cH0, mb + PLANE + cH0, mb + cH4, mb + PLANE + cH4, ms,         \
           v0[0], v0[1], v2[0], v2[1]); }                                      \
   _Pragma("unroll")                                                           \
   for (int s = 0; s < 2; s++) {                                               \
     sts3(aH0 + s * SIGB, v0[s].x, v0[s].y, v0[s].z);                          \
     sts3(aH4 + s * SIGB, v2[s].x, v2[s].y, v2[s].z);                          \
     sts3(aRE + s * SIGB, mox[s], moy[s], moz[s]);                             \
   }                                                                           \
   __syncthreads();                                                            \
   /* stage 1: rows RA, RB from buf0 (centers in regs), both sims */           \
   float cAx[2], cAy[2], cAz[2], cBx[2], cBy[2], cBz[2];                       \
   float ax[2], ay[2], az[2];                                                  \
   _Pragma("unroll")                                                           \
   for (int s = 0; s < 2; s++) {                                               \
     cAx[s] = ty ? v0[s].x : mox[s]; cAy[s] = ty ? v0[s].y : moy[s];           \
     cAz[s] = ty ? v0[s].z : moz[s];                                           \
     cBx[s] = ty ? mox[s] : v2[s].x; cBy[s] = ty ? moy[s] : v2[s].y;           \
     cBz[s] = ty ? moz[s] : v2[s].z;                                           \
     float3 kA, kB;                                                            \
     TORQ(aRA + s * SIGB, aRAw + s * SIGB, aRAe + s * SIGB, 0,                 \
          cAx[s], cAy[s], cAz[s], bxA, byA, bzallA[s], kA);                    \
     sts3(aRA + s * SIGB + BUFB, cAx[s] + h2 * kA.x, cAy[s] + h2 * kA.y,       \
          cAz[s] + h2 * kA.z);                                                 \
     TORQ(aRB_ + s * SIGB, aRBw + s * SIGB, aRBe + s * SIGB, 0,                \
          cBx[s], cBy[s], cBz[s], bxB, byB, bzallB[s], kB);                    \
     sts3(aRB_ + s * SIGB + BUFB, cBx[s] + h2 * kB.x, cBy[s] + h2 * kB.y,      \
          cBz[s] + h2 * kB.z);                                                 \
     ax[s] = ty ? kB.x : kA.x; ay[s] = ty ? kB.y : kA.y;                       \
     az[s] = ty ? kB.z : kA.z;                                                 \
   }                                                                           \
   __syncthreads();                                                            \
   /* stage 2: own row RE from buf1; tagged u2 publish, both sims */           \
   us++;                                                                       \
   float u2x[2], u2y[2], u2z[2];                                               \
   _Pragma("unroll")                                                           \
   for (int s = 0; s < 2; s++) {                                               \
     float ex, ey, ez;                                                         \
     lds3(ex, ey, ez, aRE + s * SIGB + BUFB);                                  \
     float3 k2;                                                                \
     TORQ(aRE + s * SIGB, aREw + s * SIGB, aREe + s * SIGB, BUFB,              \
          ex, ey, ez, bxE, byE, bzallE[s], k2);                                \
     ax[s] += 2.0f * k2.x; ay[s] += 2.0f * k2.y; az[s] += 2.0f * k2.z;         \
     u2x[s] = mox[s] + h2 * k2.x; u2y[s] = moy[s] + h2 * k2.y;                 \
     u2z[s] = moz[s] + h2 * k2.z;                                              \
     stcg4(&g_u2[s][gcown], make_float4(u2x[s], u2y[s], u2z[s],                \
                                        __int_as_float((int)us)));             \
     sts3(aRE + s * SIGB + 2 * BUFB, u2x[s], u2y[s], u2z[s]);                  \
   }                                                                           \
   float4 w0[2], w2[2];                                                        \
   POLL4(&g_u2[0][cH0], &g_u2[1][cH0], &g_u2[0][cH4], &g_u2[1][cH4], us,       \
         w0[0], w0[1], w2[0], w2[1]);                                          \
   _Pragma("unroll")                                                           \
   for (int s = 0; s < 2; s++) {                                               \
     sts3(aH0 + s * SIGB + 2 * BUFB, w0[s].x, w0[s].y, w0[s].z);               \
     sts3(aH4 + s * SIGB + 2 * BUFB, w2[s].x, w2[s].y, w2[s].z);               \
   }                                                                           \
   __syncthreads();                                                            \
   /* stage 3: rows RA, RB from buf2 (centers in regs), both sims */           \
   _Pragma("unroll")                                                           \
   for (int s = 0; s < 2; s++) {                                               \
     float dAx = ty ? w0[s].x : u2x[s], dAy = ty ? w0[s].y : u2y[s],           \
           dAz = ty ? w0[s].z : u2z[s];                                        \
     float dBx = ty ? u2x[s] : w2[s].x, dBy = ty ? u2y[s] : w2[s].y,           \
           dBz = ty ? u2z[s] : w2[s].z;                                        \
     float3 kA, kB;                                                            \
     TORQ(aRA + s * SIGB, aRAw + s * SIGB, aRAe + s * SIGB, 2 * BUFB,          \
          dAx, dAy, dAz, bxA, byA, bzallA[s], kA);                             \
     TORQ(aRB_ + s * SIGB, aRBw + s * SIGB, aRBe + s * SIGB, 2 * BUFB,         \
          dBx, dBy, dBz, bxB, byB, bzallB[s], kB);                             \
     sts3(aRA + s * SIGB + BUFB, cAx[s] + hh * kA.x, cAy[s] + hh * kA.y,       \
          cAz[s] + hh * kA.z);                                                 \
     sts3(aRB_ + s * SIGB + BUFB, cBx[s] + hh * kB.x, cBy[s] + hh * kB.y,      \
          cBz[s] + hh * kB.z);                                                 \
     ax[s] += 2.0f * (ty ? kB.x : kA.x);                                       \
     ay[s] += 2.0f * (ty ? kB.y : kA.y);                                       \
     az[s] += 2.0f * (ty ? kB.z : kA.z);                                       \
   }                                                                           \
   __syncthreads();                                                            \
   /* stage 4: own row RE from buf1; combine + tagged m publish, both */       \
   ms++;                                                                       \
   { float4* mbn = g_mbuf[ms & 1u][0];                                         \
     _Pragma("unroll")                                                         \
     for (int s = 0; s < 2; s++) {                                             \
       float ex, ey, ez;                                                       \
       lds3(ex, ey, ez, aRE + s * SIGB + BUFB);                                \
       float3 k4;                                                              \
       TORQ(aRE + s * SIGB, aREw + s * SIGB, aREe + s * SIGB, BUFB,            \
            ex, ey, ez, bxE, byE, bzallE[s], k4);                              \
       ax[s] += k4.x; ay[s] += k4.y; az[s] += k4.z;                            \
       mox[s] += h6 * ax[s]; moy[s] += h6 * ay[s]; moz[s] += h6 * az[s];       \
       stcg4(mbn + s * PLANE + gcown,                                          \
             make_float4(mox[s], moy[s], moz[s], __int_as_float((int)ms)));    \
     } } }

__global__ void __launch_bounds__(NT, 1)
mm_kernel(const float* __restrict__ sig, const float* __restrict__ Bext,
          const float* __restrict__ MsatP, const int* __restrict__ srcP,
          const int* __restrict__ probeP, const int* __restrict__ finalP,
          float* __restrict__ out)
{
    extern __shared__ float4 smf4[];
    uint32_t S;
    asm("{ .reg .u64 t; cvta.to.shared.u64 t, %1; cvt.u32.u64 %0, t; }"
        : "=r"(S) : "l"(smf4));

    const int tid = threadIdx.x;
    const int c   = tid & 255;
    const int ty  = tid >> 8;               // 0/1, warp-uniform
    const int r   = blockIdx.x;

    // Smem addresses (sig-0 block; sig-1 adds compile-time SIGB).
    const uint32_t cB = (uint32_t)(c + 1) * 16u;
    const int wD = (c == 0) ? 0 : -16;
    const int eD = (c == 255) ? 0 : 16;
    const uint32_t aRA  = S + (uint32_t)(2 - ty) * RBY + cB;
    const uint32_t aRB_ = S + (uint32_t)(4 - ty) * RBY + cB;
    const uint32_t aRE  = S + (uint32_t)(2 + ty) * RBY + cB;
    const uint32_t aRAw = aRA + wD,  aRAe = aRA + eD;
    const uint32_t aRBw = aRB_ + wD, aRBe = aRB_ + eD;
    const uint32_t aREw = aRE + wD,  aREe = aRE + eD;
    const uint32_t aH0  = S + (uint32_t)ty * RBY + cB;
    const uint32_t aH4  = S + (uint32_t)(4 + ty) * RBY + cB;

    // Global rows (clamped) and poll/publish cells.
    int g;
    g = 2 * r - 2 + ty;                 // window row ty (low poll)
    const int gH0 = g < 0 ? 0 : g;
    g = 2 * r + 2 + ty;                 // window row 4+ty (high poll)
    const int gH4 = g > NXg - 1 ? NXg - 1 : g;
    g = 2 * r - ty;                     // row RA -> global
    const int gRA = g < 0 ? 0 : (g > NXg - 1 ? NXg - 1 : g);
    g = 2 * r + 2 - ty;                 // row RB -> global
    const int gRB = g < 0 ? 0 : (g > NXg - 1 ? NXg - 1 : g);
    const int gRE = 2 * r + ty;         // own row
    const int cH0 = gH0 * NYg + c;
    const int cH4 = gH4 * NYg + c;
    const int gcown = gRE * NYg + c;

    // Tag bases (own sector; persisted; uniform across CTAs).
    unsigned ms = g_base[8 * r];
    unsigned us = g_base[8 * r + 1];

    const float Msat = *MsatP;
    const float CEx = (float)(2.0 * 3.5e-12 / ((double)Msat * (5e-8 * 5e-8)));
    const float CD  = (float)(4e-7 * 3.14159265358979323846 * (double)Msat);
    const float hh  = (float)(175950000000.0 * 5e-12);   // GAMMA_LL * DT
    const float h2  = 0.5f * hh;
    const float h6  = hh * (1.0f / 6.0f);
    const int final_board = *finalP;

    // B_ext at rows RA, RB, RE (shared by both sims).
    const int oRA = gRA * NYg + c, oRB = gRB * NYg + c;
    const float bxA = __ldg(Bext + 0 * PLANE + oRA);
    const float byA = __ldg(Bext + 1 * PLANE + oRA);
    const float bzA = __ldg(Bext + 2 * PLANE + oRA);
    const float bxB = __ldg(Bext + 0 * PLANE + oRB);
    const float byB = __ldg(Bext + 1 * PLANE + oRB);
    const float bzB = __ldg(Bext + 2 * PLANE + oRB);
    const float bxE = __ldg(Bext + 0 * PLANE + gcown);
    const float byE = __ldg(Bext + 1 * PLANE + gcown);
    const float bzE = __ldg(Bext + 2 * PLANE + gcown);

    // Source ids at rows RA, RB, RE.
    int sidA, sidB, sidE;
    {
        int s0r = srcP[0], s0c = srcP[1];
        int s1r = srcP[2], s1c = srcP[3];
        int s2r = srcP[4], s2c = srcP[5];
        sidA = (gRA == s0r && c == s0c) ? 0 : (gRA == s1r && c == s1c) ? 1 :
               (gRA == s2r && c == s2c) ? 2 : -1;
        sidB = (gRB == s0r && c == s0c) ? 0 : (gRB == s1r && c == s1c) ? 1 :
               (gRB == s2r && c == s2c) ? 2 : -1;
        sidE = (gRE == s0r && c == s0c) ? 0 : (gRE == s1r && c == s1c) ? 1 :
               (gRE == s2r && c == s2c) ? 2 : -1;
    }
    // Probe id at owned cell.
    int pid = -1;
    #pragma unroll
    for (int k = 0; k < NPROBE; k++)
        if (probeP[2 * k] == gRE && probeP[2 * k + 1] == c) pid = k;

    float mox[2], moy[2], moz[2];          // own m, both sims
    float bzallA[2], bzallB[2], bzallE[2]; // bz + source per sim

    // ---- init: m0 = (0,1,0) both sims; tagged publish ----
    mox[0] = mox[1] = 0.0f; moy[0] = moy[1] = 1.0f; moz[0] = moz[1] = 0.0f;
    ms++;
    {
        float4* mbn = g_mbuf[ms & 1u][0];
        stcg4(mbn + gcown, make_float4(0.0f, 1.0f, 0.0f,
                                       __int_as_float((int)ms)));
        stcg4(mbn + PLANE + gcown, make_float4(0.0f, 1.0f, 0.0f,
                                               __int_as_float((int)ms)));
    }

    // ---- relax phase: alpha = 0.5, no source (both slots identical) ----
    {
        const float alpha = 0.5f;
        const float inv = 1.0f / (1.0f + alpha * alpha);
        bzallA[0] = bzallA[1] = bzA;
        bzallB[0] = bzallB[1] = bzB;
        bzallE[0] = bzallE[1] = bzE;
        for (int s_ = 0; s_ < RELAXN; s_++) {
            STEPK();
        }
    }
    const float mrz = moz[0];   // m_relaxed z (own cell; slots identical)

    // ---- driven phase: alpha = 0.01, both signals in lockstep ----
    // Slots are already exactly at m_relaxed — no reset events needed.
    {
        const float alpha = 0.01f;
        const float inv = 1.0f / (1.0f + alpha * alpha);
        for (int t = 0; t < TSTEPS; t++) {
            #pragma unroll
            for (int s = 0; s < 2; s++) {
                const float* sp = sig + (s * TSTEPS + t) * NSRC;
                float sv0 = __ldg(sp + 0), sv1 = __ldg(sp + 1),
                      sv2 = __ldg(sp + 2);
                bzallA[s] = bzA + ((sidA == 0) ? sv0 : (sidA == 1) ? sv1 :
                                   (sidA == 2) ? sv2 : 0.0f);
                bzallB[s] = bzB + ((sidB == 0) ? sv0 : (sidB == 1) ? sv1 :
                                   (sidB == 2) ? sv2 : 0.0f);
                bzallE[s] = bzE + ((sidE == 0) ? sv0 : (sidE == 1) ? sv1 :
                                   (sidE == 2) ? sv2 : 0.0f);
            }
            STEPK();
            if (pid >= 0) {
                #pragma unroll
                for (int s = 0; s < 2; s++) {
                    float val = final_board ? (moz[s] - mrz) * Msat : moz[s];
                    out[(s * TSTEPS + t) * NPROBE + pid] = val;
                }
            }
        }
    }

    // Persist tag bases for the next graph replay (own slot only).
    if (tid == 0) {
        g_base[8 * r]     = ms;
        g_base[8 * r + 1] = us;
    }
}

extern "C" void kernel_launch(void* const* d_in, const int* in_sizes, int n_in,
                              void* d_out, int out_size) {
    const float* sig    = (const float*)d_in[0];  // (2, 256, 3)
    const float* Bext   = (const float*)d_in[1];  // (1, 3, 256, 256)
    const float* MsatP  = (const float*)d_in[2];  // scalar
    const int*   srcP   = (const int*)d_in[3];    // (3, 2)
    const int*   probeP = (const int*)d_in[4];    // (5, 2)
    const int*   finalP = (const int*)d_in[5];    // scalar
    float* out = (float*)d_out;                   // (2, 256, 5)
    (void)in_sizes; (void)n_in; (void)out_size;

    cudaFuncSetAttribute(mm_kernel,
                         cudaFuncAttributeMaxDynamicSharedMemorySize,
                         SMEM_BYTES);
    mm_kernel<<<NBLK, NT, SMEM_BYTES>>>(sig, Bext, MsatP, srcP, probeP,
                                        finalP, out);
}

// round 16
// speedup vs baseline: 1.2023x; 1.1360x over previous
#include <cuda_runtime.h>
#include <cstdint>

// Micromagnetic LLG RK4 solver — Round 16: fused-signal stepping with
// SINGLE-SIM RELAX. R15 established step = 0.63us + 0.27us/row-compute;
// relax ran both (identical) sim slots at doubled cost. Now STEPK is
// generic over sim count: relax advances one sim (NS=1), driven advances
// both signals in lockstep (NS=2). Transition publishes sig-1 m=m_relaxed
// under the current tag (publish-before-wait holds; sig-1 u2 is published
// inside driven step 1 before any poll of it).
// All other machinery is the proven R12/R14/R15 set: two-phase halo-2
// stepping, tag-in-.w neighbor sync, parity m buffers, single u2 buffer,
// monotonic tags persisted in g_base, precomputed smem addresses.
// 128 CTAs x 512 threads; CTA r owns global rows {2r,2r+1}; thread
// (ty = tid>>8, c = tid&255) owns cell (2r+ty, c) in both sims.

#define NXg 256
#define NYg 256
#define PLANE (NXg * NYg)
#define TSTEPS 256
#define NSRC 3
#define NPROBE 5
#define RELAXN 100
#define NBLK 128
#define NT 512
#define SROW 258
#define RBY 4128                  // row bytes = SROW * 16
#define BUFB (6 * RBY)            // per-buffer bytes (6 rows)
#define SIGB (3 * BUFB)           // per-sig smem block (3 buffers)
#define SMEM_BYTES (2 * SIGB)     // 148,608 B

__device__ float4 g_mbuf[2][2][PLANE];   // [parity][sig]
__device__ float4 g_u2[2][PLANE];        // [sig]
__device__ unsigned g_base[NBLK * 8];    // [8r]=m count, [8r+1]=u2 count

__device__ __forceinline__ float4 ldcg4(const float4* p) {
    float4 v;
    asm volatile("ld.global.cg.v4.f32 {%0,%1,%2,%3}, [%4];"
                 : "=f"(v.x), "=f"(v.y), "=f"(v.z), "=f"(v.w)
                 : "l"(p) : "memory");
    return v;
}
__device__ __forceinline__ void stcg4(float4* p, float4 v) {
    asm volatile("st.global.cg.v4.f32 [%0], {%1,%2,%3,%4};"
                 :: "l"(p), "f"(v.x), "f"(v.y), "f"(v.z), "f"(v.w)
                 : "memory");
}
__device__ __forceinline__ void lds3(float& x, float& y, float& z,
                                     uint32_t a) {
    float w_;
    asm volatile("ld.shared.v4.f32 {%0,%1,%2,%3}, [%4];"
                 : "=f"(x), "=f"(y), "=f"(z), "=f"(w_) : "r"(a));
}
__device__ __forceinline__ void sts3(uint32_t a, float x, float y, float z) {
    asm volatile("st.shared.v4.f32 [%0], {%1,%2,%3,%4};"
                 :: "r"(a), "f"(x), "f"(y), "f"(z), "f"(0.0f));
}

__device__ __forceinline__ float3 lap_torque(
    float ux, float uy, float uz,
    float sx, float sy, float sz,          // N+S+W+E sums
    float bx, float by, float bz_,         // bz_ already includes source
    float CEx, float CD, float alpha, float inv)
{
    float lx = sx - 4.0f * ux, ly = sy - 4.0f * uy, lz = sz - 4.0f * uz;
    float Bx = bx + CEx * lx;
    float By = by + CEx * ly;
    float Bz = bz_ + CEx * lz - CD * uz;
    float c1x = uy * Bz - uz * By;
    float c1y = uz * Bx - ux * Bz;
    float c1z = ux * By - uy * Bx;
    float c2x = uy * c1z - uz * c1y;
    float c2y = uz * c1x - ux * c1z;
    float c2z = ux * c1y - uy * c1x;
    const float CS = 1.0e-4f;
    float3 t;
    t.x = -inv * (c1x + alpha * c2x) + CS * (ux * uy);
    t.y = -inv * (c1y + alpha * c2y) + CS * (-(uz * uz + ux * ux));
    t.z = -inv * (c1z + alpha * c2z) + CS * (uy * uz);
    return t;
}

// Torque at row with center base AC (+compile-time buffer offset BO).
#define TORQ(AC, AW, AE, BO, cx, cy, cz, bx_, by_, bz_, KV)                    \
  { float n1x, n1y, n1z, n2x, n2y, n2z, wx_, wy_, wz_, ex_, ey_, ez_;          \
    lds3(n1x, n1y, n1z, (AC) + (BO) - RBY);                                    \
    lds3(n2x, n2y, n2z, (AC) + (BO) + RBY);                                    \
    lds3(wx_, wy_, wz_, (AW) + (BO));                                          \
    lds3(ex_, ey_, ez_, (AE) + (BO));                                          \
    KV = lap_torque(cx, cy, cz,                                                \
        n1x + n2x + wx_ + ex_, n1y + n2y + wy_ + ey_, n1z + n2z + wz_ + ez_,   \
        bx_, by_, bz_, CEx, CD, alpha, inv); }

// One RK4 step advancing NS sims (NS = 1 or 2, compile-time).
// Entry: own m in mo*[s]; tag ms current (all NS slots published).
#define STEPK(NS)                                                              \
 { float4 v0[2], v2[2];                                                        \
   { const float4* mb = g_mbuf[ms & 1u][0];                                    \
     bool ok;                                                                  \
     do {                                                                      \
       ok = true;                                                              \
       _Pragma("unroll")                                                       \
       for (int s = 0; s < (NS); s++) {                                        \
         v0[s] = ldcg4(mb + s * PLANE + cH0);                                  \
         v2[s] = ldcg4(mb + s * PLANE + cH4);                                  \
         ok &= (((int)(__float_as_int(v0[s].w) - (int)ms) |                    \
                 (int)(__float_as_int(v2[s].w) - (int)ms)) >= 0);              \
       }                                                                       \
     } while (!ok); }                                                          \
   _Pragma("unroll")                                                           \
   for (int s = 0; s < (NS); s++) {                                            \
     sts3(aH0 + s * SIGB, v0[s].x, v0[s].y, v0[s].z);                          \
     sts3(aH4 + s * SIGB, v2[s].x, v2[s].y, v2[s].z);                          \
     sts3(aRE + s * SIGB, mox[s], moy[s], moz[s]);                             \
   }                                                                           \
   __syncthreads();                                                            \
   /* stage 1: rows RA, RB from buf0 (centers in regs) */                      \
   float cAx[2], cAy[2], cAz[2], cBx[2], cBy[2], cBz[2];                       \
   float ax[2], ay[2], az[2];                                                  \
   _Pragma("unroll")                                                           \
   for (int s = 0; s < (NS); s++) {                                            \
     cAx[s] = ty ? v0[s].x : mox[s]; cAy[s] = ty ? v0[s].y : moy[s];           \
     cAz[s] = ty ? v0[s].z : moz[s];                                           \
     cBx[s] = ty ? mox[s] : v2[s].x; cBy[s] = ty ? moy[s] : v2[s].y;           \
     cBz[s] = ty ? moz[s] : v2[s].z;                                           \
     float3 kA, kB;                                                            \
     TORQ(aRA + s * SIGB, aRAw + s * SIGB, aRAe + s * SIGB, 0,                 \
          cAx[s], cAy[s], cAz[s], bxA, byA, bzallA[s], kA);                    \
     sts3(aRA + s * SIGB + BUFB, cAx[s] + h2 * kA.x, cAy[s] + h2 * kA.y,       \
          cAz[s] + h2 * kA.z);                                                 \
     TORQ(aRB_ + s * SIGB, aRBw + s * SIGB, aRBe + s * SIGB, 0,                \
          cBx[s], cBy[s], cBz[s], bxB, byB, bzallB[s], kB);                    \
     sts3(aRB_ + s * SIGB + BUFB, cBx[s] + h2 * kB.x, cBy[s] + h2 * kB.y,      \
          cBz[s] + h2 * kB.z);                                                 \
     ax[s] = ty ? kB.x : kA.x; ay[s] = ty ? kB.y : kA.y;                       \
     az[s] = ty ? kB.z : kA.z;                                                 \
   }                                                                           \
   __syncthreads();                                                            \
   /* stage 2: own row RE from buf1; tagged u2 publish */                      \
   us++;                                                                       \
   float u2x[2], u2y[2], u2z[2];                                               \
   _Pragma("unroll")                                                           \
   for (int s = 0; s < (NS); s++) {                                            \
     float ex, ey, ez;                                                         \
     lds3(ex, ey, ez, aRE + s * SIGB + BUFB);                                  \
     float3 k2;                                                                \
     TORQ(aRE + s * SIGB, aREw + s * SIGB, aREe + s * SIGB, BUFB,              \
          ex, ey, ez, bxE, byE, bzallE[s], k2);                                \
     ax[s] += 2.0f * k2.x; ay[s] += 2.0f * k2.y; az[s] += 2.0f * k2.z;         \
     u2x[s] = mox[s] + h2 * k2.x; u2y[s] = moy[s] + h2 * k2.y;                 \
     u2z[s] = moz[s] + h2 * k2.z;                                              \
     stcg4(&g_u2[s][gcown], make_float4(u2x[s], u2y[s], u2z[s],                \
                                        __int_as_float((int)us)));             \
     sts3(aRE + s * SIGB + 2 * BUFB, u2x[s], u2y[s], u2z[s]);                  \
   }                                                                           \
   float4 w0[2], w2[2];                                                        \
   { bool ok;                                                                  \
     do {                                                                      \
       ok = true;                                                              \
       _Pragma("unroll")                                                       \
       for (int s = 0; s < (NS); s++) {                                        \
         w0[s] = ldcg4(&g_u2[s][cH0]);                                         \
         w2[s] = ldcg4(&g_u2[s][cH4]);                                         \
         ok &= (((int)(__float_as_int(w0[s].w) - (int)us) |                    \
                 (int)(__float_as_int(w2[s].w) - (int)us)) >= 0);              \
       }                                                                       \
     } while (!ok); }                                                          \
   _Pragma("unroll")                                                           \
   for (int s = 0; s < (NS); s++) {                                            \
     sts3(aH0 + s * SIGB + 2 * BUFB, w0[s].x, w0[s].y, w0[s].z);               \
     sts3(aH4 + s * SIGB + 2 * BUFB, w2[s].x, w2[s].y, w2[s].z);               \
   }                                                                           \
   __syncthreads();                                                            \
   /* stage 3: rows RA, RB from buf2 (centers in regs) */                      \
   _Pragma("unroll")                                                           \
   for (int s = 0; s < (NS); s++) {                                            \
     float dAx = ty ? w0[s].x : u2x[s], dAy = ty ? w0[s].y : u2y[s],           \
           dAz = ty ? w0[s].z : u2z[s];                                        \
     float dBx = ty ? u2x[s] : w2[s].x, dBy = ty ? u2y[s] : w2[s].y,           \
           dBz = ty ? u2z[s] : w2[s].z;                                        \
     float3 kA, kB;                                                            \
     TORQ(aRA + s * SIGB, aRAw + s * SIGB, aRAe + s * SIGB, 2 * BUFB,          \
          dAx, dAy, dAz, bxA, byA, bzallA[s], kA);                             \
     TORQ(aRB_ + s * SIGB, aRBw + s * SIGB, aRBe + s * SIGB, 2 * BUFB,         \
          dBx, dBy, dBz, bxB, byB, bzallB[s], kB);                             \
     sts3(aRA + s * SIGB + BUFB, cAx[s] + hh * kA.x, cAy[s] + hh * kA.y,       \
          cAz[s] + hh * kA.z);                                                 \
     sts3(aRB_ + s * SIGB + BUFB, cBx[s] + hh * kB.x, cBy[s] + hh * kB.y,      \
          cBz[s] + hh * kB.z);                                                 \
     ax[s] += 2.0f * (ty ? kB.x : kA.x);                                       \
     ay[s] += 2.0f * (ty ? kB.y : kA.y);                                       \
     az[s] += 2.0f * (ty ? kB.z : kA.z);                                       \
   }                                                                           \
   __syncthreads();                                                            \
   /* stage 4: own row RE from buf1; combine + tagged m publish */             \
   ms++;                                                                       \
   { float4* mbn = g_mbuf[ms & 1u][0];                                         \
     _Pragma("unroll")                                                         \
     for (int s = 0; s < (NS); s++) {                                          \
       float ex, ey, ez;                                                       \
       lds3(ex, ey, ez, aRE + s * SIGB + BUFB);                                \
       float3 k4;                                                              \
       TORQ(aRE + s * SIGB, aREw + s * SIGB, aREe + s * SIGB, BUFB,            \
            ex, ey, ez, bxE, byE, bzallE[s], k4);                              \
       ax[s] += k4.x; ay[s] += k4.y; az[s] += k4.z;                            \
       mox[s] += h6 * ax[s]; moy[s] += h6 * ay[s]; moz[s] += h6 * az[s];       \
       stcg4(mbn + s * PLANE + gcown,                                          \
             make_float4(mox[s], moy[s], moz[s], __int_as_float((int)ms)));    \
     } } }

__global__ void __launch_bounds__(NT, 1)
mm_kernel(const float* __restrict__ sig, const float* __restrict__ Bext,
          const float* __restrict__ MsatP, const int* __restrict__ srcP,
          const int* __restrict__ probeP, const int* __restrict__ finalP,
          float* __restrict__ out)
{
    extern __shared__ float4 smf4[];
    uint32_t S;
    asm("{ .reg .u64 t; cvta.to.shared.u64 t, %1; cvt.u32.u64 %0, t; }"
        : "=r"(S) : "l"(smf4));

    const int tid = threadIdx.x;
    const int c   = tid & 255;
    const int ty  = tid >> 8;               // 0/1, warp-uniform
    const int r   = blockIdx.x;

    // Smem addresses (sig-0 block; sig-1 adds compile-time SIGB).
    const uint32_t cB = (uint32_t)(c + 1) * 16u;
    const int wD = (c == 0) ? 0 : -16;
    const int eD = (c == 255) ? 0 : 16;
    const uint32_t aRA  = S + (uint32_t)(2 - ty) * RBY + cB;
    const uint32_t aRB_ = S + (uint32_t)(4 - ty) * RBY + cB;
    const uint32_t aRE  = S + (uint32_t)(2 + ty) * RBY + cB;
    const uint32_t aRAw = aRA + wD,  aRAe = aRA + eD;
    const uint32_t aRBw = aRB_ + wD, aRBe = aRB_ + eD;
    const uint32_t aREw = aRE + wD,  aREe = aRE + eD;
    const uint32_t aH0  = S + (uint32_t)ty * RBY + cB;
    const uint32_t aH4  = S + (uint32_t)(4 + ty) * RBY + cB;

    // Global rows (clamped) and poll/publish cells.
    int g;
    g = 2 * r - 2 + ty;                 // window row ty (low poll)
    const int gH0 = g < 0 ? 0 : g;
    g = 2 * r + 2 + ty;                 // window row 4+ty (high poll)
    const int gH4 = g > NXg - 1 ? NXg - 1 : g;
    g = 2 * r - ty;                     // row RA -> global
    const int gRA = g < 0 ? 0 : (g > NXg - 1 ? NXg - 1 : g);
    g = 2 * r + 2 - ty;                 // row RB -> global
    const int gRB = g < 0 ? 0 : (g > NXg - 1 ? NXg - 1 : g);
    const int gRE = 2 * r + ty;         // own row
    const int cH0 = gH0 * NYg + c;
    const int cH4 = gH4 * NYg + c;
    const int gcown = gRE * NYg + c;

    // Tag bases (own sector; persisted; uniform across CTAs).
    unsigned ms = g_base[8 * r];
    unsigned us = g_base[8 * r + 1];

    const float Msat = *MsatP;
    const float CEx = (float)(2.0 * 3.5e-12 / ((double)Msat * (5e-8 * 5e-8)));
    const float CD  = (float)(4e-7 * 3.14159265358979323846 * (double)Msat);
    const float hh  = (float)(175950000000.0 * 5e-12);   // GAMMA_LL * DT
    const float h2  = 0.5f * hh;
    const float h6  = hh * (1.0f / 6.0f);
    const int final_board = *finalP;

    // B_ext at rows RA, RB, RE (shared by both sims).
    const int oRA = gRA * NYg + c, oRB = gRB * NYg + c;
    const float bxA = __ldg(Bext + 0 * PLANE + oRA);
    const float byA = __ldg(Bext + 1 * PLANE + oRA);
    const float bzA = __ldg(Bext + 2 * PLANE + oRA);
    const float bxB = __ldg(Bext + 0 * PLANE + oRB);
    const float byB = __ldg(Bext + 1 * PLANE + oRB);
    const float bzB = __ldg(Bext + 2 * PLANE + oRB);
    const float bxE = __ldg(Bext + 0 * PLANE + gcown);
    const float byE = __ldg(Bext + 1 * PLANE + gcown);
    const float bzE = __ldg(Bext + 2 * PLANE + gcown);

    // Source ids at rows RA, RB, RE.
    int sidA, sidB, sidE;
    {
        int s0r = srcP[0], s0c = srcP[1];
        int s1r = srcP[2], s1c = srcP[3];
        int s2r = srcP[4], s2c = srcP[5];
        sidA = (gRA == s0r && c == s0c) ? 0 : (gRA == s1r && c == s1c) ? 1 :
               (gRA == s2r && c == s2c) ? 2 : -1;
        sidB = (gRB == s0r && c == s0c) ? 0 : (gRB == s1r && c == s1c) ? 1 :
               (gRB == s2r && c == s2c) ? 2 : -1;
        sidE = (gRE == s0r && c == s0c) ? 0 : (gRE == s1r && c == s1c) ? 1 :
               (gRE == s2r && c == s2c) ? 2 : -1;
    }
    // Probe id at owned cell.
    int pid = -1;
    #pragma unroll
    for (int k = 0; k < NPROBE; k++)
        if (probeP[2 * k] == gRE && probeP[2 * k + 1] == c) pid = k;

    float mox[2], moy[2], moz[2];          // own m (slot 0 used in relax)
    float bzallA[2], bzallB[2], bzallE[2]; // bz + source per sim

    // ---- init: m0 = (0,1,0); tagged publish (sig 0 only) ----
    mox[0] = 0.0f; moy[0] = 1.0f; moz[0] = 0.0f;
    ms++;
    stcg4(g_mbuf[ms & 1u][0] + gcown,
          make_float4(0.0f, 1.0f, 0.0f, __int_as_float((int)ms)));

    // ---- relax phase: alpha = 0.5, no source, SINGLE sim ----
    {
        const float alpha = 0.5f;
        const float inv = 1.0f / (1.0f + alpha * alpha);
        bzallA[0] = bzA; bzallB[0] = bzB; bzallE[0] = bzE;
        for (int s_ = 0; s_ < RELAXN; s_++) {
            STEPK(1);
        }
    }
    const float mrz = moz[0];   // m_relaxed z (own cell)

    // ---- transition: bring sig 1 online at m_relaxed, tag ms ----
    mox[1] = mox[0]; moy[1] = moy[0]; moz[1] = moz[0];
    stcg4(g_mbuf[ms & 1u][1] + gcown,
          make_float4(mox[1], moy[1], moz[1], __int_as_float((int)ms)));

    // ---- driven phase: alpha = 0.01, both signals in lockstep ----
    {
        const float alpha = 0.01f;
        const float inv = 1.0f / (1.0f + alpha * alpha);
        for (int t = 0; t < TSTEPS; t++) {
            #pragma unroll
            for (int s = 0; s < 2; s++) {
                const float* sp = sig + (s * TSTEPS + t) * NSRC;
                float sv0 = __ldg(sp + 0), sv1 = __ldg(sp + 1),
                      sv2 = __ldg(sp + 2);
                bzallA[s] = bzA + ((sidA == 0) ? sv0 : (sidA == 1) ? sv1 :
                                   (sidA == 2) ? sv2 : 0.0f);
                bzallB[s] = bzB + ((sidB == 0) ? sv0 : (sidB == 1) ? sv1 :
                                   (sidB == 2) ? sv2 : 0.0f);
                bzallE[s] = bzE + ((sidE == 0) ? sv0 : (sidE == 1) ? sv1 :
                                   (sidE == 2) ? sv2 : 0.0f);
            }
            STEPK(2);
            if (pid >= 0) {
                #pragma unroll
                for (int s = 0; s < 2; s++) {
                    float val = final_board ? (moz[s] - mrz) * Msat : moz[s];
                    out[(s * TSTEPS + t) * NPROBE + pid] = val;
                }
            }
        }
    }

    // Persist tag bases for the next graph replay (own slot only).
    if (tid == 0) {
        g_base[8 * r]     = ms;
        g_base[8 * r + 1] = us;
    }
}

extern "C" void kernel_launch(void* const* d_in, const int* in_sizes, int n_in,
                              void* d_out, int out_size) {
    const float* sig    = (const float*)d_in[0];  // (2, 256, 3)
    const float* Bext   = (const float*)d_in[1];  // (1, 3, 256, 256)
    const float* MsatP  = (const float*)d_in[2];  // scalar
    const int*   srcP   = (const int*)d_in[3];    // (3, 2)
    const int*   probeP = (const int*)d_in[4];    // (5, 2)
    const int*   finalP = (const int*)d_in[5];    // scalar
    float* out = (float*)d_out;                   // (2, 256, 5)
    (void)in_sizes; (void)n_in; (void)out_size;

    cudaFuncSetAttribute(mm_kernel,
                         cudaFuncAttributeMaxDynamicSharedMemorySize,
                         SMEM_BYTES);
    mm_kernel<<<NBLK, NT, SMEM_BYTES>>>(sig, Bext, MsatP, srcP, probeP,
                                        finalP, out);
}